// round 17
// baseline (speedup 1.0000x reference)
#include <cuda_runtime.h>
#include <cuda_fp16.h>
#include <math.h>
#include <stdint.h>

#define BATCH 4
#define SEQ   1024
#define DM    1024
#define NH    16
#define DH    64

// Scratch (device globals — no allocation allowed)
__device__ float g_q[(size_t)BATCH*NH*SEQ*DH];   // holds q as HALF: [b*NH+h][s][d]
__device__ float g_k[(size_t)BATCH*SEQ*DH];      // holds k as HALF: [b*S+s][d]
__device__ float g_v[(size_t)BATCH*SEQ*DH];      // holds V^T as HALF: [d][b*S+j]
__device__ float g_ctx[(size_t)BATCH*SEQ*DM];    // holds ctx as HALF: [b*S+s][h*DH+d]
// half copies of GEMM operands
__device__ __half g_xh[(size_t)BATCH*SEQ*DM];    // x as half [4096][1024]
__device__ __half g_wqh[(size_t)DM*DM];          // Wq as half [1024][1024]
__device__ __half g_wkvh[(size_t)128*DM];        // [Wk;Wv] as half [128][1024]
__device__ __half g_woh[(size_t)DM*DM];          // Wo as half [1024][1024]

// ---------------------------------------------------------------------------
// helpers
// ---------------------------------------------------------------------------
__device__ __forceinline__ uint32_t f2h2(float a, float b) {
    __half2 h = __floats2half2_rn(a, b);
    return *(uint32_t*)&h;
}

__device__ __forceinline__ uint32_t hadd2u(uint32_t a, uint32_t b) {
    __half2 r = __hadd2(*(__half2*)&a, *(__half2*)&b);
    return *(uint32_t*)&r;
}

__device__ __forceinline__ uint32_t hmul2u(uint32_t a, uint32_t b) {
    __half2 r = __hmul2(*(__half2*)&a, *(__half2*)&b);
    return *(uint32_t*)&r;
}

__device__ __forceinline__ void mma_f16(float* c, const uint32_t* a, const uint32_t* b) {
    asm volatile(
        "mma.sync.aligned.m16n8k16.row.col.f32.f16.f16.f32 "
        "{%0,%1,%2,%3}, {%4,%5,%6,%7}, {%8,%9}, {%0,%1,%2,%3};\n"
        : "+f"(c[0]), "+f"(c[1]), "+f"(c[2]), "+f"(c[3])
        : "r"(a[0]), "r"(a[1]), "r"(a[2]), "r"(a[3]), "r"(b[0]), "r"(b[1]));
}

__device__ __forceinline__ void cp_async16(uint32_t smem_addr, const void* gptr) {
    asm volatile("cp.async.ca.shared.global [%0], [%1], 16;"
                 :: "r"(smem_addr), "l"(gptr));
}

// ---------------------------------------------------------------------------
// fp32 -> fp16 bulk convert (rn), float4 granularity
// ---------------------------------------------------------------------------
__global__ __launch_bounds__(256)
void f2h_kernel(const float4* __restrict__ src, uint2* __restrict__ dst, int n4)
{
    const int i = blockIdx.x * 256 + threadIdx.x;
    if (i < n4) {
        const float4 v = src[i];
        dst[i] = make_uint2(f2h2(v.x, v.y), f2h2(v.z, v.w));
    }
}

// ---------------------------------------------------------------------------
// Pure-half GEMM (fp32 accum): C = A @ B^T, cp.async 3-stage pipeline,
// one barrier per 16-k slab, no conversions in the hot loop.
// MODE 2: out(float) = ctx(half) @ Woh^T + bias
// MODE 4: fused projections: x<8 -> q(half, permuted); x==8 -> k + v^T (half).
// ---------------------------------------------------------------------------
#define GP2 12   // smem pitch in u32 (8 used per row) — conflict-free frags
#define STG 3

template<int MODE>
__global__ __launch_bounds__(256, 2)
void gemm_h(const __half* __restrict__ A, const __half* __restrict__ B,
            const __half* __restrict__ Bkv, const float* __restrict__ bias,
            float* __restrict__ Cf, __half* __restrict__ Cq,
            __half* __restrict__ Ck, __half* __restrict__ Cv,
            int M, int N, int K)
{
    __shared__ uint32_t sA[STG * 128 * GP2];
    __shared__ uint32_t sB[STG * 128 * GP2];

    const int tid  = threadIdx.x;
    const int lane = tid & 31;
    const int w    = tid >> 5;
    const int wr   = w >> 1;
    const int wc   = w & 1;
    const int g    = lane >> 2;
    const int t    = lane & 3;
    const int m0   = blockIdx.y * 128;
    const bool kv  = (MODE == 4) && (blockIdx.x == 8);
    const int n0   = kv ? 0 : blockIdx.x * 128;

    const __half* Bp = kv ? Bkv : (B + (size_t)n0 * K);

    const uint32_t aBase = (uint32_t)__cvta_generic_to_shared(sA);
    const uint32_t bBase = (uint32_t)__cvta_generic_to_shared(sB);

    const int crow = tid >> 1;        // 0..127
    const int cch  = tid & 1;         // 16B chunk within 32B slab-row

    float acc[2][8][4];
    #pragma unroll
    for (int mt = 0; mt < 2; mt++)
        #pragma unroll
        for (int nt = 0; nt < 8; nt++)
            #pragma unroll
            for (int q = 0; q < 4; q++) acc[mt][nt][q] = 0.f;

    const __half* aRow = A + (size_t)(m0 + crow) * K + cch * 8;
    const __half* bRow = Bp + (size_t)crow * K + cch * 8;
    const uint32_t aDst = aBase + (crow * GP2 + cch * 4) * 4;
    const uint32_t bDst = bBase + (crow * GP2 + cch * 4) * 4;

    // prologue: slabs 0,1
    #pragma unroll
    for (int s = 0; s < 2; s++) {
        cp_async16(aDst + s * (128 * GP2 * 4), aRow + s * 16);
        cp_async16(bDst + s * (128 * GP2 * 4), bRow + s * 16);
        asm volatile("cp.async.commit_group;");
    }

    const int nIt = K >> 4;
    for (int it = 0; it < nIt; it++) {
        if (it == nIt - 1) asm volatile("cp.async.wait_group 0;" ::: "memory");
        else               asm volatile("cp.async.wait_group 1;" ::: "memory");
        __syncthreads();

        // issue slab it+2 into stage (it+2)%3 (overlaps MMA below)
        if (it + 2 < nIt) {
            const int stg = (it + 2) % STG;
            cp_async16(aDst + stg * (128 * GP2 * 4), aRow + (it + 2) * 16);
            cp_async16(bDst + stg * (128 * GP2 * 4), bRow + (it + 2) * 16);
            asm volatile("cp.async.commit_group;");
        }

        const uint32_t* cA = sA + (it % STG) * 128 * GP2;
        const uint32_t* cB = sB + (it % STG) * 128 * GP2;

        uint32_t af[2][4], bf[8][2];
        #pragma unroll
        for (int mt = 0; mt < 2; mt++) {
            const int mr = wr * 32 + mt * 16;
            af[mt][0] = cA[(mr + g) * GP2 + t];
            af[mt][1] = cA[(mr + g + 8) * GP2 + t];
            af[mt][2] = cA[(mr + g) * GP2 + t + 4];
            af[mt][3] = cA[(mr + g + 8) * GP2 + t + 4];
        }
        #pragma unroll
        for (int nt = 0; nt < 8; nt++) {
            const int nn = wc * 64 + nt * 8 + g;
            bf[nt][0] = cB[nn * GP2 + t];
            bf[nt][1] = cB[nn * GP2 + t + 4];
        }
        #pragma unroll
        for (int mt = 0; mt < 2; mt++)
            #pragma unroll
            for (int nt = 0; nt < 8; nt++)
                mma_f16(acc[mt][nt], af[mt], bf[nt]);

        __syncthreads();   // all reads of stage it%3 done before its reuse
    }

    // epilogue
    #pragma unroll
    for (int mt = 0; mt < 2; mt++) {
        #pragma unroll
        for (int rr = 0; rr < 2; rr++) {
            const int m = m0 + wr * 32 + mt * 16 + g + rr * 8;
            #pragma unroll
            for (int nt = 0; nt < 8; nt++) {
                const int n = n0 + wc * 64 + nt * 8 + 2 * t;
                const float v0 = acc[mt][nt][rr * 2 + 0];
                const float v1 = acc[mt][nt][rr * 2 + 1];
                if (MODE == 2) {
                    *(float2*)&Cf[(size_t)m * N + n] =
                        make_float2(v0 + bias[n], v1 + bias[n + 1]);
                } else if (MODE == 4 && !kv) {
                    const int b = m >> 10, s = m & 1023;
                    const int h = n >> 6, d = n & 63;
                    *(uint32_t*)&Cq[(((size_t)(b * NH + h)) * SEQ + s) * DH + d] =
                        f2h2(v0, v1);
                } else {
                    const int nn = nt * 8 + 2 * t;
                    if (!wc) {
                        *(uint32_t*)&Ck[(size_t)m * 64 + nn] = f2h2(v0, v1);
                    } else {
                        Cv[(size_t)nn * 4096 + m]       = __float2half_rn(v0);
                        Cv[(size_t)(nn + 1) * 4096 + m] = __float2half_rn(v1);
                    }
                }
            }
        }
    }
}

// ---------------------------------------------------------------------------
// Fused attention (R15, unchanged): fp16 MMA, KR = HADD2, cp.async V,
// half in/out. One CTA per query i; 8 warps = (batch, half); 2 CTAs/SM.
// ---------------------------------------------------------------------------
#define QP 36   // pitch in u32 (half2) units

#define SMU_Q   (64 * QP)
#define SMU_KR  (256 * QP)
#define SMU_V   (256 * QP)
#define SMU_P   (64 * QP)
#define SMU_TOT (SMU_Q + SMU_KR + SMU_V + SMU_P + 256)
#define SM_ATTN_BYTES (SMU_TOT * 4)

__global__ __launch_bounds__(256, 2)
void attn_kernel(const float* __restrict__ rel,
                 const float* __restrict__ qbf,
                 const float* __restrict__ kbf,
                 const float* __restrict__ vtf,
                 float* __restrict__ ctxf)
{
    extern __shared__ uint32_t smu[];
    uint32_t* sQ   = smu;
    uint32_t* sKR  = sQ + SMU_Q;
    uint32_t* sV   = sKR + SMU_KR;
    uint32_t* sP   = sV + SMU_V;
    float*    sExM = (float*)(sP + SMU_P);
    float*    sExS = sExM + 128;

    const __half* qh = (const __half*)qbf;
    const __half* kh = (const __half*)kbf;
    const __half* vt = (const __half*)vtf;
    __half*       ch = (__half*)ctxf;

    const int i    = blockIdx.x;
    const int tid  = threadIdx.x;
    const int lane = tid & 31;
    const int w    = tid >> 5;
    const int b    = w >> 1;
    const int half = w & 1;
    const int g    = lane >> 2;
    const int t    = lane & 3;
    const unsigned FULL = 0xffffffffu;

    const uint32_t sV_base = (uint32_t)__cvta_generic_to_shared(sV);

    // Load Q (half) -> sQ, scaled by 1/8 (exact in fp16)
    {
        const uint32_t eighth = f2h2(0.125f, 0.125f);
        #pragma unroll
        for (int tix = 0; tix < 4; tix++) {
            const int idx = tix * 256 + tid;
            const int r  = idx >> 4;
            const int c4 = idx & 15;
            const uint2 v = *(const uint2*)&qh[((size_t)r * SEQ + i) * DH + c4 * 4];
            *(uint2*)&sQ[r * QP + c4 * 2] =
                make_uint2(hmul2u(v.x, eighth), hmul2u(v.y, eighth));
        }
    }

    float4 relbuf[4];
    #pragma unroll
    for (int tix = 0; tix < 4; tix++) {
        const int idx = tix * 256 + tid;
        const int j  = idx >> 4;
        const int d4 = (idx & 15) * 4;
        relbuf[tix] = *(const float4*)&rel[((size_t)i * SEQ + j) * DH + d4];
    }

    float mr0 = -INFINITY, mr1 = -INFINITY, lr0 = 0.f, lr1 = 0.f;
    float cacc[4][4];
    #pragma unroll
    for (int nt = 0; nt < 4; nt++)
        #pragma unroll
        for (int q = 0; q < 4; q++) cacc[nt][q] = 0.f;

    for (int j0 = 0; j0 < SEQ; j0 += 64) {
        __syncthreads();   // S0

        // V^T half: cp.async now (consumed after S3)
        #pragma unroll
        for (int tix = 0; tix < 8; tix++) {
            const int idx = tix * 256 + tid;
            const int row = idx >> 3;
            const int c8  = idx & 7;
            const int bb  = row >> 6;
            const int d   = row & 63;
            cp_async16(sV_base + (row * QP + c8 * 4) * 4,
                       &vt[(size_t)d * 4096 + bb * 1024 + j0 + c8 * 8]);
        }
        asm volatile("cp.async.commit_group;");

        // KR[b][j][d] = HADD2(K_h, rel_h)
        #pragma unroll
        for (int tix = 0; tix < 4; tix++) {
            const int idx = tix * 256 + tid;
            const int j  = idx >> 4;
            const int c4 = idx & 15;
            const int d4 = c4 * 4;
            const float4 rv = relbuf[tix];
            const uint32_t r0 = f2h2(rv.x, rv.y);
            const uint32_t r1 = f2h2(rv.z, rv.w);
            #pragma unroll
            for (int bb = 0; bb < 4; bb++) {
                const uint2 k2 = *(const uint2*)&kh[((size_t)(bb * SEQ) + j0 + j) * DH + d4];
                *(uint2*)&sKR[(bb * 64 + j) * QP + c4 * 2] =
                    make_uint2(hadd2u(k2.x, r0), hadd2u(k2.y, r1));
            }
        }
        __syncthreads();   // S1

        if (j0 + 64 < SEQ) {
            #pragma unroll
            for (int tix = 0; tix < 4; tix++) {
                const int idx = tix * 256 + tid;
                const int j  = idx >> 4;
                const int d4 = (idx & 15) * 4;
                relbuf[tix] =
                    *(const float4*)&rel[((size_t)i * SEQ + j0 + 64 + j) * DH + d4];
            }
        }

        // scores MMA
        float pr[4][4];
        #pragma unroll
        for (int nt = 0; nt < 4; nt++)
            #pragma unroll
            for (int q = 0; q < 4; q++) pr[nt][q] = 0.f;

        #pragma unroll
        for (int ks = 0; ks < 4; ks++) {
            const int kq = ks * 8;
            uint32_t af[4], bf[2];
            af[0] = sQ[(b * 16 + g) * QP + kq + t];
            af[1] = sQ[(b * 16 + g + 8) * QP + kq + t];
            af[2] = sQ[(b * 16 + g) * QP + kq + t + 4];
            af[3] = sQ[(b * 16 + g + 8) * QP + kq + t + 4];
            #pragma unroll
            for (int nt = 0; nt < 4; nt++) {
                const int n = half * 32 + nt * 8 + g;
                bf[0] = sKR[(b * 64 + n) * QP + kq + t];
                bf[1] = sKR[(b * 64 + n) * QP + kq + t + 4];
                mma_f16(pr[nt], af, bf);
            }
        }

        // row max + cross-half exchange
        float m0 = -INFINITY, m1 = -INFINITY;
        #pragma unroll
        for (int nt = 0; nt < 4; nt++) {
            m0 = fmaxf(m0, fmaxf(pr[nt][0], pr[nt][1]));
            m1 = fmaxf(m1, fmaxf(pr[nt][2], pr[nt][3]));
        }
        m0 = fmaxf(m0, __shfl_xor_sync(FULL, m0, 1));
        m0 = fmaxf(m0, __shfl_xor_sync(FULL, m0, 2));
        m1 = fmaxf(m1, __shfl_xor_sync(FULL, m1, 1));
        m1 = fmaxf(m1, __shfl_xor_sync(FULL, m1, 2));
        if (t == 0) {
            sExM[w * 16 + g]     = m0;
            sExM[w * 16 + 8 + g] = m1;
        }
        __syncthreads();   // S2

        const float pm0 = sExM[(w ^ 1) * 16 + g];
        const float pm1 = sExM[(w ^ 1) * 16 + 8 + g];
        const float mn0 = fmaxf(mr0, fmaxf(m0, pm0));
        const float mn1 = fmaxf(mr1, fmaxf(m1, pm1));
        const float corr0 = __expf(mr0 - mn0);
        const float corr1 = __expf(mr1 - mn1);
        mr0 = mn0; mr1 = mn1;

        // exp + P write + row sums
        float s0 = 0.f, s1 = 0.f;
        #pragma unroll
        for (int nt = 0; nt < 4; nt++) {
            float p0 = __expf(pr[nt][0] - mn0);
            float p1 = __expf(pr[nt][1] - mn0);
            float p2 = __expf(pr[nt][2] - mn1);
            float p3 = __expf(pr[nt][3] - mn1);
            s0 += p0 + p1; s1 += p2 + p3;
            const int jq = half * 16 + nt * 4 + t;
            sP[(b * 16 + g) * QP + jq]     = f2h2(p0, p1);
            sP[(b * 16 + g + 8) * QP + jq] = f2h2(p2, p3);
        }
        s0 += __shfl_xor_sync(FULL, s0, 1);
        s0 += __shfl_xor_sync(FULL, s0, 2);
        s1 += __shfl_xor_sync(FULL, s1, 1);
        s1 += __shfl_xor_sync(FULL, s1, 2);
        if (t == 0) {
            sExS[w * 16 + g]     = s0;
            sExS[w * 16 + 8 + g] = s1;
        }

        asm volatile("cp.async.wait_group 0;" ::: "memory");
        __syncthreads();   // S3

        lr0 = lr0 * corr0 + s0 + sExS[(w ^ 1) * 16 + g];
        lr1 = lr1 * corr1 + s1 + sExS[(w ^ 1) * 16 + 8 + g];

        // rescale ctx + AV MMA
        #pragma unroll
        for (int nt = 0; nt < 4; nt++) {
            cacc[nt][0] *= corr0; cacc[nt][1] *= corr0;
            cacc[nt][2] *= corr1; cacc[nt][3] *= corr1;
        }
        #pragma unroll
        for (int ks = 0; ks < 4; ks++) {
            const int kq = ks * 8;
            uint32_t af[4], bf[2];
            af[0] = sP[(b * 16 + g) * QP + kq + t];
            af[1] = sP[(b * 16 + g + 8) * QP + kq + t];
            af[2] = sP[(b * 16 + g) * QP + kq + t + 4];
            af[3] = sP[(b * 16 + g + 8) * QP + kq + t + 4];
            #pragma unroll
            for (int nt = 0; nt < 4; nt++) {
                const int n = half * 32 + nt * 8 + g;
                bf[0] = sV[(b * 64 + n) * QP + kq + t];
                bf[1] = sV[(b * 64 + n) * QP + kq + t + 4];
                mma_f16(cacc[nt], af, bf);
            }
        }
    }

    // epilogue: normalize + write ctx as HALF
    {
        const float inv0 = 1.f / lr0;
        const float inv1 = 1.f / lr1;
        const size_t base = ((size_t)(b * SEQ) + i) * DM;
        #pragma unroll
        for (int nt = 0; nt < 4; nt++) {
            const int d = half * 32 + nt * 8 + 2 * t;
            *(uint32_t*)&ch[base + g * DH + d] =
                f2h2(cacc[nt][0] * inv0, cacc[nt][1] * inv0);
            *(uint32_t*)&ch[base + (g + 8) * DH + d] =
                f2h2(cacc[nt][2] * inv1, cacc[nt][3] * inv1);
        }
    }
}

// ---------------------------------------------------------------------------
extern "C" void kernel_launch(void* const* d_in, const int* in_sizes, int n_in,
                              void* d_out, int out_size)
{
    const float* x   = (const float*)d_in[0];
    const float* rel = (const float*)d_in[1];
    const float* Wq  = (const float*)d_in[2];
    const float* Wk  = (const float*)d_in[3];
    const float* Wv  = (const float*)d_in[4];
    const float* Wo  = (const float*)d_in[5];
    const float* bo  = (const float*)d_in[6];
    float* out = (float*)d_out;

    float *qb, *kb, *vb, *ctx;
    __half *xh, *wqh, *wkvh, *woh;
    cudaGetSymbolAddress((void**)&qb,   g_q);
    cudaGetSymbolAddress((void**)&kb,   g_k);
    cudaGetSymbolAddress((void**)&vb,   g_v);
    cudaGetSymbolAddress((void**)&ctx,  g_ctx);
    cudaGetSymbolAddress((void**)&xh,   g_xh);
    cudaGetSymbolAddress((void**)&wqh,  g_wqh);
    cudaGetSymbolAddress((void**)&wkvh, g_wkvh);
    cudaGetSymbolAddress((void**)&woh,  g_woh);

    cudaFuncSetAttribute(attn_kernel,
                         cudaFuncAttributeMaxDynamicSharedMemorySize,
                         SM_ATTN_BYTES);

    const int M = BATCH * SEQ;  // 4096

    // bulk fp32 -> fp16 converts (rn), same rounding as before, done once
    f2h_kernel<<<(M * DM / 4 + 255) / 256, 256>>>(
        (const float4*)x, (uint2*)xh, M * DM / 4);
    f2h_kernel<<<(DM * DM / 4 + 255) / 256, 256>>>(
        (const float4*)Wq, (uint2*)wqh, DM * DM / 4);
    f2h_kernel<<<(DH * DM / 4 + 255) / 256, 256>>>(
        (const float4*)Wk, (uint2*)wkvh, DH * DM / 4);
    f2h_kernel<<<(DH * DM / 4 + 255) / 256, 256>>>(
        (const float4*)Wv, (uint2*)(wkvh + (size_t)DH * DM), DH * DM / 4);
    f2h_kernel<<<(DM * DM / 4 + 255) / 256, 256>>>(
        (const float4*)Wo, (uint2*)woh, DM * DM / 4);

    // fused q|k|v projections: x=0..7 -> q(half, permuted); x=8 -> k,v^T (half)
    {
        dim3 grid(9, M / 128);
        gemm_h<4><<<grid, 256>>>(xh, wqh, wkvh, nullptr,
                                 nullptr, (__half*)qb, (__half*)kb, (__half*)vb,
                                 M, DM, DM);
    }
    // fused attention (fp16 MMA, cp.async V, half in/out)
    attn_kernel<<<SEQ, 256, SM_ATTN_BYTES>>>(rel, qb, kb, vb, ctx);

    // out = ctx(half) @ Woh^T + bo
    {
        dim3 grid(8, M / 128);
        gemm_h<2><<<grid, 256>>>((const __half*)ctx, woh, nullptr, bo,
                                 out, nullptr, nullptr, nullptr,
                                 M, DM, DM);
    }
}